// round 9
// baseline (speedup 1.0000x reference)
#include <cuda_runtime.h>

#define HH 2048
#define WW 2048
#define HWT (HH*WW)
#define RD 7
#define RG 60
#define KSEL 4195u          /* (H*W)//1000 + 1 : rank of threshold (1-based from top) */
#define OMEGA 0.95f
#define EPSG 1e-4f

// ---------------- scratch (device globals; no allocation) ----------------
__device__ float    g_dch[HWT];            // horizontal-min intermediate
__device__ float    g_dc[HWT];             // dark channel
__device__ unsigned g_hist1[2048];         // coarse bins: float bits >> 19
__device__ unsigned g_hist2b[524288];      // fine bins: low 19 bits (within coarse bin)
__device__ unsigned g_chunk[1024];         // 512-bin chunk sums of g_hist2b
__device__ unsigned g_selKey;
__device__ unsigned g_selRank;
__device__ float    g_thres;
__device__ unsigned g_cnt;
__device__ float    g_sumr, g_sumg, g_sumb;
__device__ float    g_avg, g_invavg;

// ---------------- init: zero histograms / accumulators ----------------
__global__ void k_init() {
    int i = blockIdx.x * blockDim.x + threadIdx.x;
    if (i < 524288) g_hist2b[i] = 0u;
    if (i < 2048)   g_hist1[i]  = 0u;
    if (i < 1024)   g_chunk[i]  = 0u;
    if (i == 0) {
        g_cnt = 0u; g_sumr = 0.f; g_sumg = 0.f; g_sumb = 0.f;
        g_selKey = 0u; g_selRank = 0u; g_thres = 0.f;
    }
}

// ---------------- channel-min + horizontal min (r=7) ----------------
__global__ void __launch_bounds__(256) k_cmin_hmin(const float* __restrict__ x) {
    __shared__ float s[256 + 2*RD];
    int row = blockIdx.y;
    int x0  = blockIdx.x * 256;
    int t   = threadIdx.x;
    for (int i = t; i < 256 + 2*RD; i += 256) {
        int xx = x0 - RD + i;
        float v = 1e30f;
        if (xx >= 0 && xx < WW) {
            float r = x[0*HWT + row*WW + xx];
            float g = x[1*HWT + row*WW + xx];
            float b = x[2*HWT + row*WW + xx];
            v = fminf(r, fminf(g, b));
        }
        s[i] = v;
    }
    __syncthreads();
    float m = s[t];
#pragma unroll
    for (int j = 1; j <= 2*RD; j++) m = fminf(m, s[t + j]);
    g_dch[row*WW + x0 + t] = m;
}

// ---------------- vertical min (r=7) + fused coarse histogram ----------------
__global__ void __launch_bounds__(256) k_vmin_hist() {
    __shared__ float s[16 + 2*RD][256];
    __shared__ unsigned sh[2048];
    int t = threadIdx.x;
    for (int i = t; i < 2048; i += 256) sh[i] = 0u;
    int xx = blockIdx.x * 256 + t;
    int y0 = blockIdx.y * 16;
    for (int r = 0; r < 16 + 2*RD; r++) {
        int yy = y0 - RD + r;
        s[r][t] = (yy >= 0 && yy < HH) ? g_dch[yy*WW + xx] : 1e30f;
    }
    __syncthreads();
    int lane = t & 31;
    for (int k = 0; k < 16; k++) {
        float m = s[k][t];
#pragma unroll
        for (int j = 1; j <= 2*RD; j++) m = fminf(m, s[k + j][t]);
        g_dc[(y0 + k)*WW + xx] = m;
        unsigned key = __float_as_uint(m) >> 19;   // < 2048 for dc in [0,1)
        unsigned prev = __shfl_up_sync(0xffffffffu, key, 1);
        bool leader = (lane == 0) || (key != prev);
        unsigned bal = __ballot_sync(0xffffffffu, leader);
        if (leader) {
            unsigned above = (lane == 31) ? 0u : (bal >> (lane + 1));
            int run = above ? __ffs((int)above) : (32 - lane);
            atomicAdd(&sh[key], (unsigned)run);
        }
    }
    __syncthreads();
    for (int i = t; i < 2048; i += 256) {
        unsigned v = sh[i];
        if (v) atomicAdd(&g_hist1[i], v);
    }
}

// ---------------- find coarse bin containing the KSEL-th largest ----------------
__global__ void __launch_bounds__(256) k_scan1() {
    __shared__ unsigned part[256];
    int t = threadIdx.x;
    int hi = 2047 - 8 * t;
    unsigned sum = 0;
#pragma unroll
    for (int j = 0; j < 8; j++) sum += g_hist1[hi - j];
    part[t] = sum;
    __syncthreads();
    if (t == 0) {
        unsigned cum = 0; int sel = 0;
        for (int i = 0; i < 256; i++) {
            if (cum + part[i] >= KSEL) { sel = i; break; }
            cum += part[i];
        }
        int hb = 2047 - 8 * sel;
        for (int j = 0; j < 8; j++) {
            unsigned h = g_hist1[hb - j];
            if (cum + h >= KSEL) {
                g_selKey = (unsigned)(hb - j);
                g_selRank = KSEL - cum;
                break;
            }
            cum += h;
        }
    }
}

// ---------------- histogram pass 2: low 19 bits within selected bin (uint4) ----------------
__global__ void k_hist2() {
    unsigned B = g_selKey;
    const uint4* __restrict__ dc4 = reinterpret_cast<const uint4*>(g_dc);
    int tid = blockIdx.x * blockDim.x + threadIdx.x;
    int stride = gridDim.x * blockDim.x;
    for (int i = tid; i < HWT/4; i += stride) {
        uint4 v = dc4[i];
        if ((v.x >> 19) == B) atomicAdd(&g_hist2b[v.x & 0x7FFFFu], 1u);
        if ((v.y >> 19) == B) atomicAdd(&g_hist2b[v.y & 0x7FFFFu], 1u);
        if ((v.z >> 19) == B) atomicAdd(&g_hist2b[v.z & 0x7FFFFu], 1u);
        if ((v.w >> 19) == B) atomicAdd(&g_hist2b[v.w & 0x7FFFFu], 1u);
    }
}

// ---------------- reduce fine histogram into 1024 chunk sums (coalesced) ----------------
__global__ void __launch_bounds__(128) k_chunks() {
    __shared__ unsigned w[4];
    int b = blockIdx.x, t = threadIdx.x;
    unsigned s = 0;
#pragma unroll
    for (int k = 0; k < 4; k++) s += g_hist2b[b * 512 + k * 128 + t];
#pragma unroll
    for (int o = 16; o > 0; o >>= 1) s += __shfl_down_sync(0xffffffffu, s, o);
    if ((t & 31) == 0) w[t >> 5] = s;
    __syncthreads();
    if (t == 0) g_chunk[b] = w[0] + w[1] + w[2] + w[3];
}

// ---------------- select chunk, then exact fine bin ----------------
__global__ void __launch_bounds__(1024) k_scan2() {
    __shared__ unsigned sc[1024];
    __shared__ unsigned sb[512];
    __shared__ int selC;
    __shared__ unsigned selR;
    unsigned K = g_selRank;
    int t = threadIdx.x;
    sc[t] = g_chunk[t];                     // coalesced
    __syncthreads();
    if (t == 0) {
        unsigned cum = 0;
        for (int j = 1023; j >= 0; j--) {
            unsigned h = sc[j];
            if (cum + h >= K) { selC = j; selR = K - cum; break; }
            cum += h;
        }
    }
    __syncthreads();
    int c = selC;
    if (t < 512) sb[t] = g_hist2b[c * 512 + t];   // coalesced
    __syncthreads();
    if (t == 0) {
        unsigned K2 = selR;
        unsigned cum = 0;
        for (int j = 511; j >= 0; j--) {
            unsigned h = sb[j];
            if (cum + h >= K2) {
                g_thres = __uint_as_float((g_selKey << 19) | (unsigned)(c * 512 + j));
                break;
            }
            cum += h;
        }
    }
}

// ---------------- masked sums for atmospheric light (float4 dc) ----------------
__global__ void k_mask(const float* __restrict__ x) {
    float th = g_thres;
    const float4* __restrict__ dc4 = reinterpret_cast<const float4*>(g_dc);
    int tid = blockIdx.x * blockDim.x + threadIdx.x;
    int stride = gridDim.x * blockDim.x;
    unsigned cnt = 0; float sr = 0.f, sg = 0.f, sb = 0.f;
    for (int i = tid; i < HWT/4; i += stride) {
        float4 d = dc4[i];
        int base = i * 4;
#pragma unroll
        for (int j = 0; j < 4; j++) {
            float dv = (j == 0) ? d.x : (j == 1) ? d.y : (j == 2) ? d.z : d.w;
            if (dv >= th) {
                cnt++;
                sr += x[base + j];
                sg += x[HWT + base + j];
                sb += x[2*HWT + base + j];
            }
        }
    }
#pragma unroll
    for (int o = 16; o > 0; o >>= 1) {
        cnt += __shfl_down_sync(0xffffffffu, cnt, o);
        sr  += __shfl_down_sync(0xffffffffu, sr,  o);
        sg  += __shfl_down_sync(0xffffffffu, sg,  o);
        sb  += __shfl_down_sync(0xffffffffu, sb,  o);
    }
    if ((threadIdx.x & 31) == 0) {
        atomicAdd(&g_cnt, cnt);
        atomicAdd(&g_sumr, sr);
        atomicAdd(&g_sumg, sg);
        atomicAdd(&g_sumb, sb);
    }
}

__global__ void k_avg() {
    float c = (float)g_cnt;
    float avg = (0.299f * g_sumr + 0.587f * g_sumg + 0.114f * g_sumb) / c;
    g_avg = avg;
    g_invavg = 1.0f / avg;
}

// ================= fused guided filter =================
// block: 384 threads; output tile 256 cols x 128 rows.
// thread t owns haloed column c0-60+t (segment width 376; t>=376 idle cols).
// vertical 10-plane rolling sums in registers; per-row block scan in smem.
#define GTW 256
#define GTH 128
#define GSEG 376

__device__ __forceinline__ void gf_load(const float* __restrict__ x, int yy,
                                        int cc, bool ok, float r[4]) {
    if (ok) {
        int o = yy * WW + cc;
        r[0] = x[o]; r[1] = x[HWT + o]; r[2] = x[2*HWT + o]; r[3] = g_dc[o];
    } else {
        r[0] = 0.f; r[1] = 0.f; r[2] = 0.f; r[3] = 0.f;
    }
}

__device__ __forceinline__ void gf_planes(const float r[4], bool ok, float inva,
                                          float v[10]) {
    float p = ok ? fmaf(-OMEGA * inva, r[3], 1.0f) : 0.f;
    v[0] = p;
    v[1] = r[0]; v[2] = r[1]; v[3] = r[2];
    v[4] = p * r[0]; v[5] = p * r[1]; v[6] = p * r[2];
    v[7] = r[0] * r[0]; v[8] = r[1] * r[1]; v[9] = r[2] * r[2];
}

__global__ void __launch_bounds__(384) k_gf(const float* __restrict__ x,
                                            float* __restrict__ out) {
    __shared__ float sps[10][384];
    __shared__ float swt[10][12];
    int t = threadIdx.x, lane = t & 31, w = t >> 5;
    int c0 = blockIdx.x * GTW;
    int col = c0 - RG + t;
    bool cv = (t < GSEG) && (col >= 0) && (col < WW);
    int cc = cv ? col : 0;
    int y0 = blockIdx.y * GTH;
    float inva = g_invavg;
    float avg = g_avg;

    // vertical warm-up: rows [y0-RG, y0+RG] clipped
    float s[10];
#pragma unroll
    for (int p = 0; p < 10; p++) s[p] = 0.f;
    {
        int ylo = y0 - RG; if (ylo < 0) ylo = 0;
        int yhi = y0 + RG; if (yhi > HH - 1) yhi = HH - 1;
#pragma unroll 4
        for (int yy = ylo; yy <= yhi; yy++) {
            float r[4]; gf_load(x, yy, cc, cv, r);
            float v[10]; gf_planes(r, cv, inva, v);
#pragma unroll
            for (int p = 0; p < 10; p++) s[p] += v[p];
        }
    }

    int nx = 0;
    if (t < GTW) {
        int gc = c0 + t;
        nx = min(gc + RG, WW - 1) - max(gc - RG, 0) + 1;
    }

    // prefetch add/sub rows for k=1
    float ra[4], rs[4]; bool va, vs;
    {
        int ya = y0 + 1 + RG, yr = y0 - RG;   // y - RG - 1 at y = y0+1
        va = (ya < HH) && cv;  gf_load(x, ya, cc, va, ra);
        vs = (yr >= 0) && cv;  gf_load(x, yr, cc, vs, rs);
    }

    for (int k = 0; k < GTH; k++) {
        int y = y0 + k;
        // --- block scan of the 10 vertical sums across the segment ---
        float sc[10];
#pragma unroll
        for (int p = 0; p < 10; p++) sc[p] = s[p];
#pragma unroll
        for (int o = 1; o < 32; o <<= 1) {
#pragma unroll
            for (int p = 0; p < 10; p++) {
                float n = __shfl_up_sync(0xffffffffu, sc[p], o);
                if (lane >= o) sc[p] += n;
            }
        }
        if (lane == 31) {
#pragma unroll
            for (int p = 0; p < 10; p++) swt[p][w] = sc[p];
        }
        __syncthreads();
#pragma unroll
        for (int p = 0; p < 10; p++) {
            float off = 0.f;
#pragma unroll
            for (int j = 0; j < 11; j++) if (j < w) off += swt[p][j];
            sps[p][t] = sc[p] + off;
        }
        __syncthreads();

        // --- windowed diff + epilogue (output threads only) ---
        if (t < GTW) {
            int gc = c0 + t;
            float wv[10];
#pragma unroll
            for (int p = 0; p < 10; p++)
                wv[p] = sps[p][t + 2*RG] - (t > 0 ? sps[p][t - 1] : 0.f);
            int ny = min(y + RG, HH - 1) - max(y - RG, 0) + 1;
            float invN = __fdividef(1.0f, (float)(nx * ny));
            float mp = wv[0] * invN;
            int base = y * WW + gc;
#pragma unroll
            for (int ch = 0; ch < 3; ch++) {
                float mi  = wv[1 + ch] * invN;
                float mpi = wv[4 + ch] * invN;
                float mii = wv[7 + ch] * invN;
                float cip = mpi - mp * mi;
                float cii = mii - mi * mi;
                float a = __fdividef(cip, cii + EPSG);
                float b = mp - a * mi;
                float xi = x[ch * HWT + base];
                float rt = fminf(fmaxf(a * xi + b, 0.0f), 1.0f);
                rt = fmaxf(rt, 0.1f);
                float yv = __fdividef(xi - avg, rt) + avg;
                out[ch * HWT + base] = fminf(fmaxf(yv, 0.0f), 1.0f);
            }
        }

        // --- vertical update for next row (prefetched) + prefetch k+2 ---
        if (k + 1 < GTH) {
            float vA[10], vS[10];
            gf_planes(ra, va, inva, vA);
            gf_planes(rs, vs, inva, vS);
#pragma unroll
            for (int p = 0; p < 10; p++) s[p] += vA[p] - vS[p];
            int ya = y0 + k + 2 + RG, yr = y0 + k + 1 - RG;
            va = (ya < HH) && cv;  gf_load(x, ya, cc, va, ra);
            vs = (yr >= 0) && cv;  gf_load(x, yr, cc, vs, rs);
        }
        __syncthreads();
    }
}

// ---------------- launch ----------------
extern "C" void kernel_launch(void* const* d_in, const int* in_sizes, int n_in,
                              void* d_out, int out_size) {
    const float* x = (const float*)d_in[0];
    float* out = (float*)d_out;

    k_init<<<2048, 256>>>();
    k_cmin_hmin<<<dim3(8, 2048), 256>>>(x);
    k_vmin_hist<<<dim3(8, 128), 256>>>();
    k_scan1<<<1, 256>>>();
    k_hist2<<<1024, 256>>>();
    k_chunks<<<1024, 128>>>();
    k_scan2<<<1, 1024>>>();
    k_mask<<<1024, 256>>>(x);
    k_avg<<<1, 1>>>();
    k_gf<<<dim3(WW/GTW, HH/GTH), 384>>>(x, out);
}

// round 11
// speedup vs baseline: 1.0381x; 1.0381x over previous
#include <cuda_runtime.h>

#define HH 2048
#define WW 2048
#define HWT (HH*WW)
#define RD 7
#define RG 60
#define KSEL 4195u          /* (H*W)//1000 + 1 : rank of threshold (1-based from top) */
#define OMEGA 0.95f
#define EPSG 1e-4f

// ---------------- scratch (device globals; no allocation) ----------------
__device__ float    g_dch[HWT];            // horizontal-min intermediate
__device__ float    g_dc[HWT];             // dark channel
__device__ float    g_vsum[10*HWT];        // 10 vertically box-summed planes (160MB)
__device__ unsigned g_hist1[2048];         // coarse bins: float bits >> 19
__device__ unsigned g_hist2b[524288];      // fine bins: low 19 bits (within coarse bin)
__device__ unsigned g_chunk[1024];         // 512-bin chunk sums of g_hist2b
__device__ unsigned g_selKey;
__device__ unsigned g_selRank;
__device__ float    g_thres;
__device__ unsigned g_cnt;
__device__ float    g_sumr, g_sumg, g_sumb;
__device__ float    g_avg, g_invavg;

// ---------------- init: zero histograms / accumulators ----------------
__global__ void k_init() {
    int i = blockIdx.x * blockDim.x + threadIdx.x;
    if (i < 524288) g_hist2b[i] = 0u;
    if (i < 2048)   g_hist1[i]  = 0u;
    if (i < 1024)   g_chunk[i]  = 0u;
    if (i == 0) {
        g_cnt = 0u; g_sumr = 0.f; g_sumg = 0.f; g_sumb = 0.f;
        g_selKey = 0u; g_selRank = 0u; g_thres = 0.f;
    }
}

// ---------------- channel-min + horizontal min (r=7) ----------------
__global__ void __launch_bounds__(256) k_cmin_hmin(const float* __restrict__ x) {
    __shared__ float s[256 + 2*RD];
    int row = blockIdx.y;
    int x0  = blockIdx.x * 256;
    int t   = threadIdx.x;
    for (int i = t; i < 256 + 2*RD; i += 256) {
        int xx = x0 - RD + i;
        float v = 1e30f;
        if (xx >= 0 && xx < WW) {
            float r = x[0*HWT + row*WW + xx];
            float g = x[1*HWT + row*WW + xx];
            float b = x[2*HWT + row*WW + xx];
            v = fminf(r, fminf(g, b));
        }
        s[i] = v;
    }
    __syncthreads();
    float m = s[t];
#pragma unroll
    for (int j = 1; j <= 2*RD; j++) m = fminf(m, s[t + j]);
    g_dch[row*WW + x0 + t] = m;
}

// ---------------- vertical min (r=7) + fused coarse histogram ----------------
__global__ void __launch_bounds__(256) k_vmin_hist() {
    __shared__ float s[16 + 2*RD][256];
    __shared__ unsigned sh[2048];
    int t = threadIdx.x;
    for (int i = t; i < 2048; i += 256) sh[i] = 0u;
    int xx = blockIdx.x * 256 + t;
    int y0 = blockIdx.y * 16;
    for (int r = 0; r < 16 + 2*RD; r++) {
        int yy = y0 - RD + r;
        s[r][t] = (yy >= 0 && yy < HH) ? g_dch[yy*WW + xx] : 1e30f;
    }
    __syncthreads();
    int lane = t & 31;
    for (int k = 0; k < 16; k++) {
        float m = s[k][t];
#pragma unroll
        for (int j = 1; j <= 2*RD; j++) m = fminf(m, s[k + j][t]);
        g_dc[(y0 + k)*WW + xx] = m;
        unsigned key = __float_as_uint(m) >> 19;   // < 2048 for dc in [0,1)
        unsigned prev = __shfl_up_sync(0xffffffffu, key, 1);
        bool leader = (lane == 0) || (key != prev);
        unsigned bal = __ballot_sync(0xffffffffu, leader);
        if (leader) {
            unsigned above = (lane == 31) ? 0u : (bal >> (lane + 1));
            int run = above ? __ffs((int)above) : (32 - lane);
            atomicAdd(&sh[key], (unsigned)run);
        }
    }
    __syncthreads();
    for (int i = t; i < 2048; i += 256) {
        unsigned v = sh[i];
        if (v) atomicAdd(&g_hist1[i], v);
    }
}

// ---------------- find coarse bin containing the KSEL-th largest ----------------
__global__ void __launch_bounds__(256) k_scan1() {
    __shared__ unsigned part[256];
    int t = threadIdx.x;
    int hi = 2047 - 8 * t;
    unsigned sum = 0;
#pragma unroll
    for (int j = 0; j < 8; j++) sum += g_hist1[hi - j];
    part[t] = sum;
    __syncthreads();
    if (t == 0) {
        unsigned cum = 0; int sel = 0;
        for (int i = 0; i < 256; i++) {
            if (cum + part[i] >= KSEL) { sel = i; break; }
            cum += part[i];
        }
        int hb = 2047 - 8 * sel;
        for (int j = 0; j < 8; j++) {
            unsigned h = g_hist1[hb - j];
            if (cum + h >= KSEL) {
                g_selKey = (unsigned)(hb - j);
                g_selRank = KSEL - cum;
                break;
            }
            cum += h;
        }
    }
}

// ---------------- histogram pass 2: low 19 bits within selected bin (uint4) ----------------
__global__ void k_hist2() {
    unsigned B = g_selKey;
    const uint4* __restrict__ dc4 = reinterpret_cast<const uint4*>(g_dc);
    int tid = blockIdx.x * blockDim.x + threadIdx.x;
    int stride = gridDim.x * blockDim.x;
    for (int i = tid; i < HWT/4; i += stride) {
        uint4 v = dc4[i];
        if ((v.x >> 19) == B) atomicAdd(&g_hist2b[v.x & 0x7FFFFu], 1u);
        if ((v.y >> 19) == B) atomicAdd(&g_hist2b[v.y & 0x7FFFFu], 1u);
        if ((v.z >> 19) == B) atomicAdd(&g_hist2b[v.z & 0x7FFFFu], 1u);
        if ((v.w >> 19) == B) atomicAdd(&g_hist2b[v.w & 0x7FFFFu], 1u);
    }
}

// ---------------- reduce fine histogram into 1024 chunk sums (coalesced) ----------------
__global__ void __launch_bounds__(128) k_chunks() {
    __shared__ unsigned w[4];
    int b = blockIdx.x, t = threadIdx.x;
    unsigned s = 0;
#pragma unroll
    for (int k = 0; k < 4; k++) s += g_hist2b[b * 512 + k * 128 + t];
#pragma unroll
    for (int o = 16; o > 0; o >>= 1) s += __shfl_down_sync(0xffffffffu, s, o);
    if ((t & 31) == 0) w[t >> 5] = s;
    __syncthreads();
    if (t == 0) g_chunk[b] = w[0] + w[1] + w[2] + w[3];
}

// ---------------- select chunk, then exact fine bin ----------------
__global__ void __launch_bounds__(1024) k_scan2() {
    __shared__ unsigned sc[1024];
    __shared__ unsigned sb[512];
    __shared__ int selC;
    __shared__ unsigned selR;
    unsigned K = g_selRank;
    int t = threadIdx.x;
    sc[t] = g_chunk[t];                     // coalesced
    __syncthreads();
    if (t == 0) {
        unsigned cum = 0;
        for (int j = 1023; j >= 0; j--) {
            unsigned h = sc[j];
            if (cum + h >= K) { selC = j; selR = K - cum; break; }
            cum += h;
        }
    }
    __syncthreads();
    int c = selC;
    if (t < 512) sb[t] = g_hist2b[c * 512 + t];   // coalesced
    __syncthreads();
    if (t == 0) {
        unsigned K2 = selR;
        unsigned cum = 0;
        for (int j = 511; j >= 0; j--) {
            unsigned h = sb[j];
            if (cum + h >= K2) {
                g_thres = __uint_as_float((g_selKey << 19) | (unsigned)(c * 512 + j));
                break;
            }
            cum += h;
        }
    }
}

// ---------------- masked sums for atmospheric light (float4 dc) ----------------
__global__ void k_mask(const float* __restrict__ x) {
    float th = g_thres;
    const float4* __restrict__ dc4 = reinterpret_cast<const float4*>(g_dc);
    int tid = blockIdx.x * blockDim.x + threadIdx.x;
    int stride = gridDim.x * blockDim.x;
    unsigned cnt = 0; float sr = 0.f, sg = 0.f, sb = 0.f;
    for (int i = tid; i < HWT/4; i += stride) {
        float4 d = dc4[i];
        int base = i * 4;
#pragma unroll
        for (int j = 0; j < 4; j++) {
            float dv = (j == 0) ? d.x : (j == 1) ? d.y : (j == 2) ? d.z : d.w;
            if (dv >= th) {
                cnt++;
                sr += x[base + j];
                sg += x[HWT + base + j];
                sb += x[2*HWT + base + j];
            }
        }
    }
#pragma unroll
    for (int o = 16; o > 0; o >>= 1) {
        cnt += __shfl_down_sync(0xffffffffu, cnt, o);
        sr  += __shfl_down_sync(0xffffffffu, sr,  o);
        sg  += __shfl_down_sync(0xffffffffu, sg,  o);
        sb  += __shfl_down_sync(0xffffffffu, sb,  o);
    }
    if ((threadIdx.x & 31) == 0) {
        atomicAdd(&g_cnt, cnt);
        atomicAdd(&g_sumr, sr);
        atomicAdd(&g_sumg, sg);
        atomicAdd(&g_sumb, sb);
    }
}

__global__ void k_avg() {
    float c = (float)g_cnt;
    float avg = (0.299f * g_sumr + 0.587f * g_sumg + 0.114f * g_sumb) / c;
    g_avg = avg;
    g_invavg = 1.0f / avg;
}

// ---------------- helpers for the vertical pass ----------------
__device__ __forceinline__ void vload(const float* __restrict__ x, int yy, int c,
                                      float r[4]) {
    int o = yy * WW + c;
    r[0] = x[o]; r[1] = x[HWT + o]; r[2] = x[2*HWT + o]; r[3] = g_dc[o];
}

__device__ __forceinline__ void vplanes(const float r[4], float inva, float v[10]) {
    float p = fmaf(-OMEGA * inva, r[3], 1.0f);
    v[0] = p;
    v[1] = r[0]; v[2] = r[1]; v[3] = r[2];
    v[4] = p * r[0]; v[5] = p * r[1]; v[6] = p * r[2];
    v[7] = r[0] * r[0]; v[8] = r[1] * r[1]; v[9] = r[2] * r[2];
}

// ---------------- vertical rolling box sums of the 10 planes ----------------
#define VS 32
__global__ void __launch_bounds__(256) k_vpass(const float* __restrict__ x) {
    int c  = blockIdx.x * 256 + threadIdx.x;
    int y0 = blockIdx.y * VS;
    float inva = g_invavg;
    float s[10];
#pragma unroll
    for (int p = 0; p < 10; p++) s[p] = 0.f;

    bool interior = (y0 >= RG + 1) && (y0 + VS - 1 + RG < HH);

    int ylo = y0 - RG; if (ylo < 0) ylo = 0;
    int yhi = y0 + RG; if (yhi > HH - 1) yhi = HH - 1;
#pragma unroll 4
    for (int yy = ylo; yy <= yhi; yy++) {
        float r[4]; vload(x, yy, c, r);
        float v[10]; vplanes(r, inva, v);
#pragma unroll
        for (int p = 0; p < 10; p++) s[p] += v[p];
    }

    if (interior) {
        // prefetch rows for k=1
        float ra[4], rs[4];
        vload(x, y0 + 1 + RG, c, ra);
        vload(x, y0 - RG, c, rs);
        // store row y0
#pragma unroll
        for (int p = 0; p < 10; p++)
            g_vsum[p*HWT + y0*WW + c] = s[p];
        for (int k = 1; k < VS; k++) {
            int y = y0 + k;
            float vA[10], vS[10];
            vplanes(ra, inva, vA);
            vplanes(rs, inva, vS);
#pragma unroll
            for (int p = 0; p < 10; p++) s[p] += vA[p] - vS[p];
            // prefetch next row-pair BEFORE the stores so the LDGs overlap them
            if (k + 1 < VS) {
                vload(x, y + 1 + RG, c, ra);
                vload(x, y - RG, c, rs);
            }
#pragma unroll
            for (int p = 0; p < 10; p++)
                g_vsum[p*HWT + y*WW + c] = s[p];
        }
    } else {
        for (int k = 0; k < VS; k++) {
            int y = y0 + k;
            if (k > 0) {
                int ya = y + RG;
                if (ya < HH) {
                    float r[4]; vload(x, ya, c, r);
                    float v[10]; vplanes(r, inva, v);
#pragma unroll
                    for (int p = 0; p < 10; p++) s[p] += v[p];
                }
                int yr = y - RG - 1;
                if (yr >= 0) {
                    float r[4]; vload(x, yr, c, r);
                    float v[10]; vplanes(r, inva, v);
#pragma unroll
                    for (int p = 0; p < 10; p++) s[p] -= v[p];
                }
            }
#pragma unroll
            for (int p = 0; p < 10; p++)
                g_vsum[p*HWT + y*WW + c] = s[p];
        }
    }
}

// ---------------- horizontal box sums (block scans, 2 planes/round) + epilogue ----------------
// one block per half-row: 1024 output cols + 60-col halo each side, zero-padded
#define SEG 1144
__global__ void __launch_bounds__(256) k_hfinal(const float* __restrict__ x,
                                                float* __restrict__ out) {
    __shared__ float sps[10][SEG];
    __shared__ float2 wpart[8];
    int row = blockIdx.y;
    int c0  = blockIdx.x * 1024;
    int s0  = c0 - RG;
    int t = threadIdx.x, lane = t & 31, wid = t >> 5;

    for (int pl = 0; pl < 10; pl += 2) {
        const float* __restrict__ srcA = g_vsum + (pl+0)*HWT + row*WW;
        const float* __restrict__ srcB = g_vsum + (pl+1)*HWT + row*WW;
        float carryA = 0.f, carryB = 0.f;
        for (int ch = 0; ch < 5; ch++) {
            int L = ch * 256 + t;
            int gc = s0 + L;
            float vA = 0.f, vB = 0.f;
            bool in = (L < SEG && gc >= 0 && gc < WW);
            if (in) { vA = srcA[gc]; vB = srcB[gc]; }
            float scA = vA, scB = vB;
#pragma unroll
            for (int o = 1; o < 32; o <<= 1) {
                float nA = __shfl_up_sync(0xffffffffu, scA, o);
                float nB = __shfl_up_sync(0xffffffffu, scB, o);
                if (lane >= o) { scA += nA; scB += nB; }
            }
            if (lane == 31) wpart[wid] = make_float2(scA, scB);
            __syncthreads();
            float offA = carryA, offB = carryB, totA = 0.f, totB = 0.f;
#pragma unroll
            for (int w = 0; w < 8; w++) {
                float2 pw = wpart[w];
                totA += pw.x; totB += pw.y;
                if (w < wid) { offA += pw.x; offB += pw.y; }
            }
            if (L < SEG) {
                sps[pl+0][L] = scA + offA;
                sps[pl+1][L] = scB + offB;
            }
            carryA += totA; carryB += totB;
            __syncthreads();
        }
    }

    float avg = g_avg;
    int ny = min(row + RG, HH - 1) - max(row - RG, 0) + 1;
#pragma unroll
    for (int j = 0; j < 4; j++) {
        int L = t + j * 256;          // 0..1023
        int gc = c0 + L;
        int hi = L + 2*RG;            // local index of gc+RG
        int lo = L - 1;               // local index of gc-RG-1
        float w0 = sps[0][hi] - (lo >= 0 ? sps[0][lo] : 0.f);
        float w1 = sps[1][hi] - (lo >= 0 ? sps[1][lo] : 0.f);
        float w2 = sps[2][hi] - (lo >= 0 ? sps[2][lo] : 0.f);
        float w3 = sps[3][hi] - (lo >= 0 ? sps[3][lo] : 0.f);
        float w4 = sps[4][hi] - (lo >= 0 ? sps[4][lo] : 0.f);
        float w5 = sps[5][hi] - (lo >= 0 ? sps[5][lo] : 0.f);
        float w6 = sps[6][hi] - (lo >= 0 ? sps[6][lo] : 0.f);
        float w7 = sps[7][hi] - (lo >= 0 ? sps[7][lo] : 0.f);
        float w8 = sps[8][hi] - (lo >= 0 ? sps[8][lo] : 0.f);
        float w9 = sps[9][hi] - (lo >= 0 ? sps[9][lo] : 0.f);
        int nx = min(gc + RG, WW - 1) - max(gc - RG, 0) + 1;
        float invN = __fdividef(1.0f, (float)(nx * ny));
        float mp = w0 * invN;
        float mi, mpi, mii, cip, cii, a, b, xi, rt, yv;
        // ch 0
        mi = w1 * invN; mpi = w4 * invN; mii = w7 * invN;
        cip = mpi - mp * mi; cii = mii - mi * mi;
        a = __fdividef(cip, cii + EPSG); b = mp - a * mi;
        xi = x[0*HWT + row*WW + gc];
        rt = fminf(fmaxf(a * xi + b, 0.0f), 1.0f); rt = fmaxf(rt, 0.1f);
        yv = __fdividef(xi - avg, rt) + avg;
        out[0*HWT + row*WW + gc] = fminf(fmaxf(yv, 0.0f), 1.0f);
        // ch 1
        mi = w2 * invN; mpi = w5 * invN; mii = w8 * invN;
        cip = mpi - mp * mi; cii = mii - mi * mi;
        a = __fdividef(cip, cii + EPSG); b = mp - a * mi;
        xi = x[1*HWT + row*WW + gc];
        rt = fminf(fmaxf(a * xi + b, 0.0f), 1.0f); rt = fmaxf(rt, 0.1f);
        yv = __fdividef(xi - avg, rt) + avg;
        out[1*HWT + row*WW + gc] = fminf(fmaxf(yv, 0.0f), 1.0f);
        // ch 2
        mi = w3 * invN; mpi = w6 * invN; mii = w9 * invN;
        cip = mpi - mp * mi; cii = mii - mi * mi;
        a = __fdividef(cip, cii + EPSG); b = mp - a * mi;
        xi = x[2*HWT + row*WW + gc];
        rt = fminf(fmaxf(a * xi + b, 0.0f), 1.0f); rt = fmaxf(rt, 0.1f);
        yv = __fdividef(xi - avg, rt) + avg;
        out[2*HWT + row*WW + gc] = fminf(fmaxf(yv, 0.0f), 1.0f);
    }
}

// ---------------- launch ----------------
extern "C" void kernel_launch(void* const* d_in, const int* in_sizes, int n_in,
                              void* d_out, int out_size) {
    const float* x = (const float*)d_in[0];
    float* out = (float*)d_out;

    k_init<<<2048, 256>>>();
    k_cmin_hmin<<<dim3(8, 2048), 256>>>(x);
    k_vmin_hist<<<dim3(8, 128), 256>>>();
    k_scan1<<<1, 256>>>();
    k_hist2<<<1024, 256>>>();
    k_chunks<<<1024, 128>>>();
    k_scan2<<<1, 1024>>>();
    k_mask<<<1024, 256>>>(x);
    k_avg<<<1, 1>>>();
    k_vpass<<<dim3(8, 64), 256>>>(x);
    k_hfinal<<<dim3(2, 2048), 256>>>(x, out);
}